// round 2
// baseline (speedup 1.0000x reference)
#include <cuda_runtime.h>

#define N_TOK 65536
#define D_IN  1024
#define E_DIM 256
#define K_CB  1024
#define EPS   1e-5f
#define SLABS 64

// ---------------- scratch (device globals; no runtime allocation) ----------------
__device__ float g_ps1[SLABS * D_IN];
__device__ float g_ps2[SLABS * D_IN];
__device__ float g_a[D_IN];
__device__ float g_bv[D_IN];
__device__ float g_w1s[E_DIM * D_IN];
__device__ float g_b1p[E_DIM];
__device__ float g_h[(size_t)N_TOK * E_DIM];          // 64 MB
__device__ float g_hh[N_TOK];
__device__ float g_ee[K_CB];
__device__ unsigned long long g_amin[N_TOK];
__device__ int   g_hist[K_CB];
__device__ float g_scale2[E_DIM];
__device__ float g_shift2[E_DIM];
__device__ float g_qn[K_CB * E_DIM];
__device__ float g_ocb[(size_t)K_CB * D_IN];          // 4 MB out-codebook
__device__ double g_loss;

// ---------------- init ----------------
__global__ void k_init() {
    int i = blockIdx.x * blockDim.x + threadIdx.x;   // 65536 threads
    g_amin[i] = 0xFFFFFFFFFFFFFFFFull;
    if (i < K_CB) g_hist[i] = 0;
    if (i == 0)   g_loss = 0.0;
}

// ---------------- BN1 column stats (deterministic two-stage) ----------------
__global__ void k_colstats(const float* __restrict__ x) {
    int col  = blockIdx.x * 256 + threadIdx.x;
    int slab = blockIdx.y;
    const float* p = x + (size_t)slab * 1024 * D_IN + col;
    float s = 0.f, s2 = 0.f;
#pragma unroll 8
    for (int r = 0; r < 1024; r++) {
        float v = p[(size_t)r * D_IN];
        s += v; s2 += v * v;
    }
    g_ps1[slab * D_IN + col] = s;
    g_ps2[slab * D_IN + col] = s2;
}

__global__ void k_bn1fin(const float* __restrict__ gamma1, const float* __restrict__ beta1) {
    int col = blockIdx.x * 256 + threadIdx.x;
    float s = 0.f, s2 = 0.f;
    for (int i = 0; i < SLABS; i++) { s += g_ps1[i * D_IN + col]; s2 += g_ps2[i * D_IN + col]; }
    float mu  = s / (float)N_TOK;
    float var = s2 / (float)N_TOK - mu * mu;
    float a = gamma1[col] * rsqrtf(var + EPS);
    g_a[col]  = a;
    g_bv[col] = beta1[col] - mu * a;
}

// ---------------- fold BN1 into w1 ----------------
__global__ void k_fold(const float* __restrict__ w1, const float* __restrict__ b1) {
    int e = blockIdx.x, t = threadIdx.x;
    float acc = 0.f;
#pragma unroll
    for (int j = 0; j < D_IN / 256; j++) {
        int d = j * 256 + t;
        float w = w1[(size_t)e * D_IN + d];
        g_w1s[(size_t)e * D_IN + d] = w * g_a[d];
        acc += g_bv[d] * w;
    }
    __shared__ float sm[256];
    sm[t] = acc; __syncthreads();
    for (int s = 128; s > 0; s >>= 1) { if (t < s) sm[t] += sm[t + s]; __syncthreads(); }
    if (t == 0) g_b1p[e] = b1[e] + sm[0];
}

// ---------------- generic 128x128 NT fp32 GEMM core ----------------
__device__ __forceinline__ void gemm_nt_core(
    const float* __restrict__ A, const float* __restrict__ B,
    int Kd, int ldA, int ldB, float acc[8][8],
    float As[16][128], float Bs[16][128])
{
    int tid = threadIdx.x;
    int tx = tid & 15, ty = tid >> 4;
    const float* Ab = A + (size_t)(blockIdx.x * 128) * ldA;
    const float* Bb = B + (size_t)(blockIdx.y * 128) * ldB;
    for (int k0 = 0; k0 < Kd; k0 += 16) {
#pragma unroll
        for (int i = 0; i < 2; i++) {
            int id  = tid + i * 256;
            int row = id >> 2;
            int kq  = (id & 3) << 2;
            float4 va = *(const float4*)(Ab + (size_t)row * ldA + k0 + kq);
            As[kq + 0][row] = va.x; As[kq + 1][row] = va.y;
            As[kq + 2][row] = va.z; As[kq + 3][row] = va.w;
            float4 vb = *(const float4*)(Bb + (size_t)row * ldB + k0 + kq);
            Bs[kq + 0][row] = vb.x; Bs[kq + 1][row] = vb.y;
            Bs[kq + 2][row] = vb.z; Bs[kq + 3][row] = vb.w;
        }
        __syncthreads();
#pragma unroll
        for (int kk = 0; kk < 16; kk++) {
            float ra[8], rb[8];
            *(float4*)&ra[0] = *(const float4*)&As[kk][ty * 8];
            *(float4*)&ra[4] = *(const float4*)&As[kk][ty * 8 + 4];
            *(float4*)&rb[0] = *(const float4*)&Bs[kk][tx * 8];
            *(float4*)&rb[4] = *(const float4*)&Bs[kk][tx * 8 + 4];
#pragma unroll
            for (int i = 0; i < 8; i++)
#pragma unroll
                for (int j = 0; j < 8; j++)
                    acc[i][j] += ra[i] * rb[j];
        }
        __syncthreads();
    }
}

__device__ __forceinline__ void gemm_bias_store(
    const float* __restrict__ bias, float* __restrict__ C, int ldC, float acc[8][8])
{
    int tid = threadIdx.x;
    int tx = tid & 15, ty = tid >> 4;
    int colBase = blockIdx.y * 128 + tx * 8;
    float bv[8];
#pragma unroll
    for (int j = 0; j < 8; j++) bv[j] = bias[colBase + j];
#pragma unroll
    for (int i = 0; i < 8; i++) {
        size_t row = (size_t)blockIdx.x * 128 + ty * 8 + i;
        float4 v0, v1;
        v0.x = acc[i][0] + bv[0]; v0.y = acc[i][1] + bv[1];
        v0.z = acc[i][2] + bv[2]; v0.w = acc[i][3] + bv[3];
        v1.x = acc[i][4] + bv[4]; v1.y = acc[i][5] + bv[5];
        v1.z = acc[i][6] + bv[6]; v1.w = acc[i][7] + bv[7];
        *(float4*)(C + row * ldC + colBase)     = v0;
        *(float4*)(C + row * ldC + colBase + 4) = v1;
    }
}

// GEMM1: h = x @ w1s^T + bias1'
__global__ void k_gemm1(const float* __restrict__ x) {
    __shared__ float As[16][128];
    __shared__ float Bs[16][128];
    float acc[8][8] = {};
    gemm_nt_core(x, g_w1s, D_IN, D_IN, D_IN, acc, As, Bs);
    gemm_bias_store(g_b1p, g_h, E_DIM, acc);
}

// GEMM2: out_codebook = qn @ w2^T + b2   (K x D, reduction E)
__global__ void k_gemm2(const float* __restrict__ w2, const float* __restrict__ b2) {
    __shared__ float As[16][128];
    __shared__ float Bs[16][128];
    float acc[8][8] = {};
    gemm_nt_core(g_qn, w2, E_DIM, E_DIM, E_DIM, acc, As, Bs);
    gemm_bias_store(b2, g_ocb, D_IN, acc);
}

// ---------------- row sum-of-squares (warp per row, fixed order) ----------------
__device__ __forceinline__ void rowss_core(const float* __restrict__ M, float* __restrict__ out) {
    int warp = threadIdx.x >> 5, lane = threadIdx.x & 31;
    int row = blockIdx.x * 8 + warp;
    const float* p = M + (size_t)row * E_DIM;
    float s = 0.f;
#pragma unroll
    for (int c = lane; c < E_DIM; c += 32) { float v = p[c]; s += v * v; }
#pragma unroll
    for (int o = 16; o > 0; o >>= 1) s += __shfl_down_sync(0xffffffffu, s, o);
    if (lane == 0) out[row] = s;
}
__global__ void k_hh() { rowss_core(g_h, g_hh); }
__global__ void k_ee(const float* __restrict__ emb) { rowss_core(emb, g_ee); }

// ---------------- dist GEMM + fused argmin ----------------
__global__ void k_dist(const float* __restrict__ emb) {
    __shared__ float As[16][128];
    __shared__ float Bs[16][128];
    __shared__ unsigned long long Red[128][16];
    float acc[8][8] = {};
    gemm_nt_core(g_h, emb, E_DIM, E_DIM, E_DIM, acc, As, Bs);
    int tid = threadIdx.x;
    int tx = tid & 15, ty = tid >> 4;
    int colBase = blockIdx.y * 128 + tx * 8;
    float ee[8];
#pragma unroll
    for (int j = 0; j < 8; j++) ee[j] = g_ee[colBase + j];
#pragma unroll
    for (int i = 0; i < 8; i++) {
        int row = blockIdx.x * 128 + ty * 8 + i;
        float hh = g_hh[row];
        float best = __int_as_float(0x7f800000);
        int bi = 0;
#pragma unroll
        for (int j = 0; j < 8; j++) {
            // replicate reference rounding exactly: (hh+ee) - 2*g, no FMA contraction
            float d = __fsub_rn(__fadd_rn(hh, ee[j]), __fmul_rn(2.0f, acc[i][j]));
            if (d < best) { best = d; bi = colBase + j; }
        }
        unsigned u = __float_as_uint(best);
        u = (u & 0x80000000u) ? ~u : (u | 0x80000000u);
        Red[ty * 8 + i][tx] = ((unsigned long long)u << 32) | (unsigned)bi;
    }
    __syncthreads();
    if (tid < 128) {
        unsigned long long m = Red[tid][0];
#pragma unroll
        for (int t = 1; t < 16; t++) { unsigned long long v = Red[tid][t]; if (v < m) m = v; }
        atomicMin(&g_amin[blockIdx.x * 128 + tid], m);
    }
}

// ---------------- usage histogram ----------------
__global__ void k_histo() {
    __shared__ int sh[K_CB];
    int t = threadIdx.x;
    for (int i = t; i < K_CB; i += 256) sh[i] = 0;
    __syncthreads();
    int n = blockIdx.x * 256 + t;
    int idx = (int)(g_amin[n] & 0xFFFFFFFFull);
    atomicAdd(&sh[idx], 1);
    __syncthreads();
    for (int i = t; i < K_CB; i += 256) if (sh[i]) atomicAdd(&g_hist[i], sh[i]);
}

// ---------------- BN2 stats from usage-weighted codebook moments ----------------
__global__ void k_bn2(const float* __restrict__ emb,
                      const float* __restrict__ gamma2, const float* __restrict__ beta2) {
    int e = blockIdx.x, t = threadIdx.x;
    float s1 = 0.f, s2 = 0.f;
#pragma unroll
    for (int j = 0; j < 4; j++) {
        int k = j * 256 + t;
        float c = (float)g_hist[k];
        float v = emb[(size_t)k * E_DIM + e];
        s1 += c * v; s2 += c * v * v;
    }
    __shared__ float a1[256], a2[256];
    a1[t] = s1; a2[t] = s2; __syncthreads();
    for (int s = 128; s > 0; s >>= 1) {
        if (t < s) { a1[t] += a1[t + s]; a2[t] += a2[t + s]; }
        __syncthreads();
    }
    if (t == 0) {
        float mu  = a1[0] / (float)N_TOK;
        float var = a2[0] / (float)N_TOK - mu * mu;
        float sc = gamma2[e] * rsqrtf(var + EPS);
        g_scale2[e] = sc;
        g_shift2[e] = beta2[e] - mu * sc;
    }
}

__global__ void k_qn(const float* __restrict__ emb) {
    int i = blockIdx.x * 256 + threadIdx.x;     // K*E = 262144
    int e = i & (E_DIM - 1);
    g_qn[i] = emb[i] * g_scale2[e] + g_shift2[e];
}

// ---------------- gather + straight-through + loss ----------------
// quantized lives at out[1 .. 1+N*D): 4-byte aligned only -> scalar stores.
__global__ void k_final(const float* __restrict__ x, float* __restrict__ out) {
    int t = threadIdx.x;
    float* outq = out + 1;
    double accd = 0.0;
#pragma unroll
    for (int r = 0; r < 8; r++) {
        int n = blockIdx.x * 8 + r;
        int idx = (int)(g_amin[n] & 0xFFFFFFFFull);
        float4 q  = ((const float4*)(g_ocb + (size_t)idx * D_IN))[t];
        float4 xv = ((const float4*)(x + (size_t)n * D_IN))[t];
        float dx = __fsub_rn(q.x, xv.x);
        float dy = __fsub_rn(q.y, xv.y);
        float dz = __fsub_rn(q.z, xv.z);
        float dw = __fsub_rn(q.w, xv.w);
        float* o = outq + (size_t)n * D_IN + t * 4;
        o[0] = __fadd_rn(xv.x, dx);
        o[1] = __fadd_rn(xv.y, dy);
        o[2] = __fadd_rn(xv.z, dz);
        o[3] = __fadd_rn(xv.w, dw);
        accd += (double)dx * dx + (double)dy * dy + (double)dz * dz + (double)dw * dw;
    }
    __shared__ double sd[256];
    sd[t] = accd; __syncthreads();
    for (int s = 128; s > 0; s >>= 1) { if (t < s) sd[t] += sd[t + s]; __syncthreads(); }
    if (t == 0) atomicAdd(&g_loss, sd[0]);
}

// ---------------- small outputs ----------------
__global__ void k_small(float* __restrict__ out) {
    int i = blockIdx.x * 256 + threadIdx.x;
    size_t OFF_U = 1 + (size_t)N_TOK * D_IN;
    if (i == 0) out[0] = (float)(1.25 * g_loss / ((double)N_TOK * (double)D_IN));
    if (i < K_CB) out[OFF_U + i] = (float)g_hist[i] / (float)N_TOK;
}

__global__ void k_embcopy(const float* __restrict__ emb, float* __restrict__ out) {
    size_t OFF_E = 1 + (size_t)N_TOK * D_IN + K_CB;
    int i = blockIdx.x * 256 + threadIdx.x;     // 262144
    out[OFF_E + i] = emb[i];
}

// ---------------- launch ----------------
extern "C" void kernel_launch(void* const* d_in, const int* in_sizes, int n_in,
                              void* d_out, int out_size) {
    (void)in_sizes; (void)n_in; (void)out_size;
    const float* x      = (const float*)d_in[0];
    const float* emb    = (const float*)d_in[1];
    const float* w1     = (const float*)d_in[2];
    const float* b1     = (const float*)d_in[3];
    const float* w2     = (const float*)d_in[4];
    const float* b2     = (const float*)d_in[5];
    const float* gamma1 = (const float*)d_in[6];
    const float* beta1  = (const float*)d_in[7];
    const float* gamma2 = (const float*)d_in[8];
    const float* beta2  = (const float*)d_in[9];
    float* out = (float*)d_out;

    k_init<<<256, 256>>>();
    k_colstats<<<dim3(D_IN / 256, SLABS), 256>>>(x);
    k_bn1fin<<<D_IN / 256, 256>>>(gamma1, beta1);
    k_fold<<<E_DIM, 256>>>(w1, b1);
    k_gemm1<<<dim3(N_TOK / 128, E_DIM / 128), 256>>>(x);
    k_hh<<<N_TOK / 8, 256>>>();
    k_ee<<<K_CB / 8, 256>>>(emb);
    k_dist<<<dim3(N_TOK / 128, K_CB / 128), 256>>>(emb);
    k_histo<<<N_TOK / 256, 256>>>();
    k_bn2<<<E_DIM, 256>>>(emb, gamma2, beta2);
    k_qn<<<(K_CB * E_DIM) / 256, 256>>>(emb);
    k_gemm2<<<dim3(K_CB / 128, D_IN / 128), 256>>>(w2, b2);
    k_final<<<N_TOK / 8, 256>>>(x, out);
    k_small<<<4, 256>>>(out);
    k_embcopy<<<(K_CB * E_DIM) / 256, 256>>>(emb, out);
}

// round 4
// speedup vs baseline: 1.8528x; 1.8528x over previous
#include <cuda_runtime.h>
#include <cuda_bf16.h>
#include <cstdint>

#define N_TOK 65536
#define D_IN  1024
#define E_DIM 256
#define K_CB  1024
#define EPS   1e-5f
#define SLABS 64
#define STR   20          // padded smem row stride in uint32 (40 bf16)

// ================= scratch =================
__device__ float g_ps1[SLABS * D_IN];
__device__ float g_ps2[SLABS * D_IN];
__device__ float g_a[D_IN];
__device__ float g_bv[D_IN];
__device__ float g_w1s[E_DIM * D_IN];
__device__ float g_b1p[E_DIM];
__device__ __nv_bfloat16 g_h_hi[(size_t)N_TOK * E_DIM];   // 32 MB
__device__ __nv_bfloat16 g_h_lo[(size_t)N_TOK * E_DIM];   // 32 MB
__device__ float g_hhp[2 * N_TOK];
__device__ float g_ee[K_CB];
__device__ unsigned long long g_amin[N_TOK];
__device__ int   g_hist[K_CB];
__device__ float g_scale2[E_DIM];
__device__ float g_shift2[E_DIM];
__device__ float g_qn[K_CB * E_DIM];
__device__ float g_ocb[(size_t)K_CB * D_IN];
__device__ double g_loss;

// ================= helpers =================
__device__ __forceinline__ uint32_t pack2(__nv_bfloat16 a, __nv_bfloat16 b) {
    __nv_bfloat162 t(a, b); return *(uint32_t*)&t;
}
__device__ __forceinline__ void bf16split(float v, __nv_bfloat16& hi, __nv_bfloat16& lo) {
    hi = __float2bfloat16_rn(v);
    lo = __float2bfloat16_rn(v - __bfloat162float(hi));
}
__device__ __forceinline__ void mma_bf16(float c[4], const uint32_t a[4], const uint32_t b[2]) {
    asm volatile(
        "mma.sync.aligned.m16n8k16.row.col.f32.bf16.bf16.f32 "
        "{%0,%1,%2,%3}, {%4,%5,%6,%7}, {%8,%9}, {%0,%1,%2,%3};"
        : "+f"(c[0]), "+f"(c[1]), "+f"(c[2]), "+f"(c[3])
        : "r"(a[0]), "r"(a[1]), "r"(a[2]), "r"(a[3]), "r"(b[0]), "r"(b[1]));
}
__device__ __forceinline__ unsigned long long packdi(float d, unsigned col) {
    unsigned u = __float_as_uint(d);
    u = (u & 0x80000000u) ? ~u : (u | 0x80000000u);
    return ((unsigned long long)u << 32) | col;
}
// split fp32 4-vector -> bf16 hi/lo, store into padded smem (row, k offset kq)
__device__ __forceinline__ void store_cvt(uint32_t* hi, uint32_t* lo, int row, int kq, float4 v) {
    __nv_bfloat16 h0, h1, h2, h3, l0, l1, l2, l3;
    bf16split(v.x, h0, l0); bf16split(v.y, h1, l1);
    bf16split(v.z, h2, l2); bf16split(v.w, h3, l3);
    uint2 uh; uh.x = pack2(h0, h1); uh.y = pack2(h2, h3);
    uint2 ul; ul.x = pack2(l0, l1); ul.y = pack2(l2, l3);
    *(uint2*)(hi + row * STR + (kq >> 1)) = uh;
    *(uint2*)(lo + row * STR + (kq >> 1)) = ul;
}

// load the 4 A-fragment regs / 2 B-fragment regs for one m16n8k16 step
__device__ __forceinline__ void ldfragA(uint32_t a[4], const uint32_t* S, int r, int s8, int tig) {
    a[0] = S[r * STR + s8 + tig];
    a[1] = S[(r + 8) * STR + s8 + tig];
    a[2] = S[r * STR + s8 + tig + 4];
    a[3] = S[(r + 8) * STR + s8 + tig + 4];
}
__device__ __forceinline__ void ldfragB(uint32_t b[2], const uint32_t* S, int n, int s8, int tig) {
    b[0] = S[n * STR + s8 + tig];
    b[1] = S[n * STR + s8 + tig + 4];
}

// ================= small kernels (validated in R2) =================
__global__ void k_init() {
    int i = blockIdx.x * blockDim.x + threadIdx.x;
    g_amin[i] = 0xFFFFFFFFFFFFFFFFull;
    if (i < K_CB) g_hist[i] = 0;
    if (i == 0)   g_loss = 0.0;
}

__global__ void k_colstats(const float* __restrict__ x) {
    int col  = blockIdx.x * 256 + threadIdx.x;
    int slab = blockIdx.y;
    const float* p = x + (size_t)slab * 1024 * D_IN + col;
    float s = 0.f, s2 = 0.f;
#pragma unroll 8
    for (int r = 0; r < 1024; r++) { float v = p[(size_t)r * D_IN]; s += v; s2 += v * v; }
    g_ps1[slab * D_IN + col] = s;
    g_ps2[slab * D_IN + col] = s2;
}

__global__ void k_bn1fin(const float* __restrict__ gamma1, const float* __restrict__ beta1) {
    int col = blockIdx.x * 256 + threadIdx.x;
    float s = 0.f, s2 = 0.f;
    for (int i = 0; i < SLABS; i++) { s += g_ps1[i * D_IN + col]; s2 += g_ps2[i * D_IN + col]; }
    float mu  = s / (float)N_TOK;
    float var = s2 / (float)N_TOK - mu * mu;
    float a = gamma1[col] * rsqrtf(var + EPS);
    g_a[col]  = a;
    g_bv[col] = beta1[col] - mu * a;
}

__global__ void k_fold(const float* __restrict__ w1, const float* __restrict__ b1) {
    int e = blockIdx.x, t = threadIdx.x;
    float acc = 0.f;
#pragma unroll
    for (int j = 0; j < D_IN / 256; j++) {
        int d = j * 256 + t;
        float w = w1[(size_t)e * D_IN + d];
        g_w1s[(size_t)e * D_IN + d] = w * g_a[d];
        acc += g_bv[d] * w;
    }
    __shared__ float sm[256];
    sm[t] = acc; __syncthreads();
    for (int s = 128; s > 0; s >>= 1) { if (t < s) sm[t] += sm[t + s]; __syncthreads(); }
    if (t == 0) g_b1p[e] = b1[e] + sm[0];
}

__global__ void k_ee(const float* __restrict__ emb) {
    int warp = threadIdx.x >> 5, lane = threadIdx.x & 31;
    int row = blockIdx.x * 8 + warp;
    const float* p = emb + (size_t)row * E_DIM;
    float s = 0.f;
#pragma unroll
    for (int c = lane; c < E_DIM; c += 32) { float v = p[c]; s += v * v; }
#pragma unroll
    for (int o = 16; o > 0; o >>= 1) s += __shfl_down_sync(0xffffffffu, s, o);
    if (lane == 0) g_ee[row] = s;
}

// ================= GEMM1 (HMMA bf16x3): h = x @ w1s^T + b1p =================
// grid (512, 2), 256 thr. CTA tile 128x128, warp tile 64x32.
// smem: [2 bufs][Ahi|Alo|Bhi|Blo each 128*STR u32] + hh_sm 512 floats
__global__ __launch_bounds__(256) void k_mm1(const float* __restrict__ x) {
    extern __shared__ uint32_t sm[];
    float* hh_sm = (float*)(sm + 8 * 128 * STR);
    int tid = threadIdx.x, lane = tid & 31, warp = tid >> 5;
    int wm = warp & 1, wn = warp >> 1, g = lane >> 2, tig = lane & 3;
    const float* Asrc = x + (size_t)blockIdx.x * 128 * D_IN;
    const float* Bsrc = g_w1s + (size_t)blockIdx.y * 128 * D_IN;

    // fill buffer 0
#pragma unroll
    for (int i = 0; i < 4; i++) {
        int f = tid + i * 256, row = f >> 3, kq = (f & 7) * 4;
        float4 va = *(const float4*)(Asrc + (size_t)row * D_IN + kq);
        float4 vb = *(const float4*)(Bsrc + (size_t)row * D_IN + kq);
        store_cvt(sm, sm + 128 * STR, row, kq, va);
        store_cvt(sm + 2 * 128 * STR, sm + 3 * 128 * STR, row, kq, vb);
    }
    __syncthreads();

    float acc[4][4][4] = {};
    for (int c = 0; c < 32; c++) {
        int cur = c & 1, nxt = cur ^ 1;
        float4 ra[4], rb[4];
        if (c < 31) {
#pragma unroll
            for (int i = 0; i < 4; i++) {
                int f = tid + i * 256, row = f >> 3, kq = (f & 7) * 4;
                ra[i] = *(const float4*)(Asrc + (size_t)row * D_IN + (c + 1) * 32 + kq);
                rb[i] = *(const float4*)(Bsrc + (size_t)row * D_IN + (c + 1) * 32 + kq);
            }
        }
        const uint32_t* Ah = sm + cur * 4 * 128 * STR;
        const uint32_t* Al = Ah + 128 * STR;
        const uint32_t* Bh = Ah + 2 * 128 * STR;
        const uint32_t* Bl = Ah + 3 * 128 * STR;
#pragma unroll
        for (int s = 0; s < 2; s++) {
            int s8 = s * 8;
            uint32_t ah[4][4], al[4][4], bh[4][2], bl[4][2];
#pragma unroll
            for (int mi = 0; mi < 4; mi++) {
                int r = wm * 64 + mi * 16 + g;
                ldfragA(ah[mi], Ah, r, s8, tig);
                ldfragA(al[mi], Al, r, s8, tig);
            }
#pragma unroll
            for (int ni = 0; ni < 4; ni++) {
                int n = wn * 32 + ni * 8 + g;
                ldfragB(bh[ni], Bh, n, s8, tig);
                ldfragB(bl[ni], Bl, n, s8, tig);
            }
#pragma unroll
            for (int mi = 0; mi < 4; mi++)
#pragma unroll
                for (int ni = 0; ni < 4; ni++) {
                    mma_bf16(acc[mi][ni], ah[mi], bh[ni]);
                    mma_bf16(acc[mi][ni], ah[mi], bl[ni]);
                    mma_bf16(acc[mi][ni], al[mi], bh[ni]);
                }
        }
        if (c < 31) {
            uint32_t* nAh = sm + nxt * 4 * 128 * STR;
#pragma unroll
            for (int i = 0; i < 4; i++) {
                int f = tid + i * 256, row = f >> 3, kq = (f & 7) * 4;
                store_cvt(nAh, nAh + 128 * STR, row, kq, ra[i]);
                store_cvt(nAh + 2 * 128 * STR, nAh + 3 * 128 * STR, row, kq, rb[i]);
            }
        }
        __syncthreads();
    }

    // epilogue: bias + hh partial + bf16 split of h
    int by = blockIdx.y;
    float bv0[4], bv1[4];
#pragma unroll
    for (int ni = 0; ni < 4; ni++) {
        int colg = by * 128 + wn * 32 + ni * 8 + tig * 2;
        bv0[ni] = g_b1p[colg]; bv1[ni] = g_b1p[colg + 1];
    }
#pragma unroll
    for (int mi = 0; mi < 4; mi++) {
        int rloc = wm * 64 + mi * 16 + g;
        int rowg = blockIdx.x * 128 + rloc;
        float s0 = 0.f, s1 = 0.f;
#pragma unroll
        for (int ni = 0; ni < 4; ni++) {
            int colg = by * 128 + wn * 32 + ni * 8 + tig * 2;
            float v0 = acc[mi][ni][0] + bv0[ni];
            float v1 = acc[mi][ni][1] + bv1[ni];
            float v2 = acc[mi][ni][2] + bv0[ni];
            float v3 = acc[mi][ni][3] + bv1[ni];
            s0 += v0 * v0 + v1 * v1;
            s1 += v2 * v2 + v3 * v3;
            __nv_bfloat16 h0, h1, l0, l1;
            bf16split(v0, h0, l0); bf16split(v1, h1, l1);
            *(uint32_t*)(g_h_hi + (size_t)rowg * 256 + colg) = pack2(h0, h1);
            *(uint32_t*)(g_h_lo + (size_t)rowg * 256 + colg) = pack2(l0, l1);
            bf16split(v2, h0, l0); bf16split(v3, h1, l1);
            *(uint32_t*)(g_h_hi + (size_t)(rowg + 8) * 256 + colg) = pack2(h0, h1);
            *(uint32_t*)(g_h_lo + (size_t)(rowg + 8) * 256 + colg) = pack2(l0, l1);
        }
        s0 += __shfl_xor_sync(0xffffffffu, s0, 1);
        s0 += __shfl_xor_sync(0xffffffffu, s0, 2);
        s1 += __shfl_xor_sync(0xffffffffu, s1, 1);
        s1 += __shfl_xor_sync(0xffffffffu, s1, 2);
        if (tig == 0) { hh_sm[wn * 128 + rloc] = s0; hh_sm[wn * 128 + rloc + 8] = s1; }
    }
    __syncthreads();
    if (tid < 128) {
        float hh = hh_sm[tid] + hh_sm[128 + tid] + hh_sm[256 + tid] + hh_sm[384 + tid];
        g_hhp[(size_t)by * N_TOK + blockIdx.x * 128 + tid] = hh;
    }
}

// ================= dist GEMM (HMMA bf16x3) + fused argmin =================
// grid (512, 8). A = h hi/lo (bf16, precomputed), B = emb (fp32 -> cvt).
__global__ __launch_bounds__(256) void k_dist(const float* __restrict__ emb) {
    extern __shared__ uint32_t sm[];
    int tid = threadIdx.x, lane = tid & 31, warp = tid >> 5;
    int wm = warp & 1, wn = warp >> 1, g = lane >> 2, tig = lane & 3;
    const __nv_bfloat16* AhS = g_h_hi + (size_t)blockIdx.x * 128 * 256;
    const __nv_bfloat16* AlS = g_h_lo + (size_t)blockIdx.x * 128 * 256;
    const float* Bsrc = emb + (size_t)blockIdx.y * 128 * E_DIM;

    // fill buffer 0
#pragma unroll
    for (int i = 0; i < 2; i++) {
        int f = tid + i * 256, row = f >> 2, kq = (f & 3) * 8;
        uint4 qh = *(const uint4*)(AhS + (size_t)row * 256 + kq);
        uint4 ql = *(const uint4*)(AlS + (size_t)row * 256 + kq);
        *(uint4*)(sm + row * STR + (kq >> 1)) = qh;
        *(uint4*)(sm + 128 * STR + row * STR + (kq >> 1)) = ql;
    }
#pragma unroll
    for (int i = 0; i < 4; i++) {
        int f = tid + i * 256, row = f >> 3, kq = (f & 7) * 4;
        float4 vb = *(const float4*)(Bsrc + (size_t)row * E_DIM + kq);
        store_cvt(sm + 2 * 128 * STR, sm + 3 * 128 * STR, row, kq, vb);
    }
    __syncthreads();

    float acc[4][4][4] = {};
    for (int c = 0; c < 8; c++) {
        int cur = c & 1, nxt = cur ^ 1;
        uint4 qh[2], ql[2]; float4 rb[4];
        if (c < 7) {
#pragma unroll
            for (int i = 0; i < 2; i++) {
                int f = tid + i * 256, row = f >> 2, kq = (f & 3) * 8;
                qh[i] = *(const uint4*)(AhS + (size_t)row * 256 + (c + 1) * 32 + kq);
                ql[i] = *(const uint4*)(AlS + (size_t)row * 256 + (c + 1) * 32 + kq);
            }
#pragma unroll
            for (int i = 0; i < 4; i++) {
                int f = tid + i * 256, row = f >> 3, kq = (f & 7) * 4;
                rb[i] = *(const float4*)(Bsrc + (size_t)row * E_DIM + (c + 1) * 32 + kq);
            }
        }
        const uint32_t* Ah = sm + cur * 4 * 128 * STR;
        const uint32_t* Al = Ah + 128 * STR;
        const uint32_t* Bh = Ah + 2 * 128 * STR;
        const uint32_t* Bl = Ah + 3 * 128 * STR;
#pragma unroll
        for (int s = 0; s < 2; s++) {
            int s8 = s * 8;
            uint32_t ah[4][4], al[4][4], bh[4][2], bl[4][2];
#pragma unroll
            for (int mi = 0; mi < 4; mi++) {
                int r = wm * 64 + mi * 16 + g;
                ldfragA(ah[mi], Ah, r, s8, tig);
                ldfragA(al[mi], Al, r, s8, tig);
            }
#pragma unroll
            for (int ni = 0; ni < 4; ni++) {
                int n = wn * 32 + ni * 8 + g;
                ldfragB(bh[ni], Bh, n, s8, tig);
                ldfragB(bl[ni], Bl, n, s8, tig);
            }
#pragma unroll
            for (int mi = 0; mi < 4; mi++)
#pragma unroll
                for (int ni = 0; ni < 4; ni++) {
                    mma_bf16(acc[mi][ni], ah[mi], bh[ni]);
                    mma_bf16(acc[mi][ni], ah[mi], bl[ni]);
                    mma_bf16(acc[mi][ni], al[mi], bh[ni]);
                }
        }
        if (c < 7) {
            uint32_t* nAh = sm + nxt * 4 * 128 * STR;
#pragma unroll
            for (int i = 0; i < 2; i++) {
                int f = tid + i * 256, row = f >> 2, kq = (f & 3) * 8;
                *(uint4*)(nAh + row * STR + (kq >> 1)) = qh[i];
                *(uint4*)(nAh + 128 * STR + row * STR + (kq >> 1)) = ql[i];
            }
#pragma unroll
            for (int i = 0; i < 4; i++) {
                int f = tid + i * 256, row = f >> 3, kq = (f & 7) * 4;
                store_cvt(nAh + 2 * 128 * STR, nAh + 3 * 128 * STR, row, kq, rb[i]);
            }
        }
        __syncthreads();
    }

    // epilogue: exact-fp32 dist + argmin
    int by = blockIdx.y;
#pragma unroll
    for (int mi = 0; mi < 4; mi++) {
        int rowg = blockIdx.x * 128 + wm * 64 + mi * 16 + g;
        float hh0 = g_hhp[rowg] + g_hhp[N_TOK + rowg];
        float hh1 = g_hhp[rowg + 8] + g_hhp[N_TOK + rowg + 8];
        unsigned long long b0 = ~0ull, b1 = ~0ull;
#pragma unroll
        for (int ni = 0; ni < 4; ni++) {
            int colg = by * 128 + wn * 32 + ni * 8 + tig * 2;
            float e0 = g_ee[colg], e1 = g_ee[colg + 1];
            float d0 = __fsub_rn(__fadd_rn(hh0, e0), __fmul_rn(2.0f, acc[mi][ni][0]));
            float d1 = __fsub_rn(__fadd_rn(hh0, e1), __fmul_rn(2.0f, acc[mi][ni][1]));
            float d2 = __fsub_rn(__fadd_rn(hh1, e0), __fmul_rn(2.0f, acc[mi][ni][2]));
            float d3 = __fsub_rn(__fadd_rn(hh1, e1), __fmul_rn(2.0f, acc[mi][ni][3]));
            unsigned long long p;
            p = packdi(d0, colg);     if (p < b0) b0 = p;
            p = packdi(d1, colg + 1); if (p < b0) b0 = p;
            p = packdi(d2, colg);     if (p < b1) b1 = p;
            p = packdi(d3, colg + 1); if (p < b1) b1 = p;
        }
        unsigned long long t;
        t = __shfl_xor_sync(0xffffffffu, b0, 1); if (t < b0) b0 = t;
        t = __shfl_xor_sync(0xffffffffu, b0, 2); if (t < b0) b0 = t;
        t = __shfl_xor_sync(0xffffffffu, b1, 1); if (t < b1) b1 = t;
        t = __shfl_xor_sync(0xffffffffu, b1, 2); if (t < b1) b1 = t;
        if (tig == 0) {
            atomicMin(&g_amin[rowg], b0);
            atomicMin(&g_amin[rowg + 8], b1);
        }
    }
}

// ================= remaining pipeline (validated in R2) =================
__global__ void k_histo() {
    __shared__ int sh[K_CB];
    int t = threadIdx.x;
    for (int i = t; i < K_CB; i += 256) sh[i] = 0;
    __syncthreads();
    int n = blockIdx.x * 256 + t;
    int idx = (int)(g_amin[n] & 0xFFFFFFFFull);
    atomicAdd(&sh[idx], 1);
    __syncthreads();
    for (int i = t; i < K_CB; i += 256) if (sh[i]) atomicAdd(&g_hist[i], sh[i]);
}

__global__ void k_bn2(const float* __restrict__ emb,
                      const float* __restrict__ gamma2, const float* __restrict__ beta2) {
    int e = blockIdx.x, t = threadIdx.x;
    float s1 = 0.f, s2 = 0.f;
#pragma unroll
    for (int j = 0; j < 4; j++) {
        int k = j * 256 + t;
        float c = (float)g_hist[k];
        float v = emb[(size_t)k * E_DIM + e];
        s1 += c * v; s2 += c * v * v;
    }
    __shared__ float a1[256], a2[256];
    a1[t] = s1; a2[t] = s2; __syncthreads();
    for (int s = 128; s > 0; s >>= 1) {
        if (t < s) { a1[t] += a1[t + s]; a2[t] += a2[t + s]; }
        __syncthreads();
    }
    if (t == 0) {
        float mu  = a1[0] / (float)N_TOK;
        float var = a2[0] / (float)N_TOK - mu * mu;
        float sc = gamma2[e] * rsqrtf(var + EPS);
        g_scale2[e] = sc;
        g_shift2[e] = beta2[e] - mu * sc;
    }
}

__global__ void k_qn(const float* __restrict__ emb) {
    int i = blockIdx.x * 256 + threadIdx.x;
    int e = i & (E_DIM - 1);
    g_qn[i] = emb[i] * g_scale2[e] + g_shift2[e];
}

__global__ void k_gemm2(const float* __restrict__ w2, const float* __restrict__ b2) {
    __shared__ float As[16][128];
    __shared__ float Bs[16][128];
    float acc[8][8] = {};
    int tid = threadIdx.x;
    int tx = tid & 15, ty = tid >> 4;
    const float* Ab = g_qn + (size_t)(blockIdx.x * 128) * E_DIM;
    const float* Bb = w2 + (size_t)(blockIdx.y * 128) * E_DIM;
    for (int k0 = 0; k0 < E_DIM; k0 += 16) {
#pragma unroll
        for (int i = 0; i < 2; i++) {
            int id  = tid + i * 256;
            int row = id >> 2;
            int kq  = (id & 3) << 2;
            float4 va = *(const float4*)(Ab + (size_t)row * E_DIM + k0 + kq);
            As[kq + 0][row] = va.x; As[kq + 1][row] = va.y;
            As[kq + 2][row] = va.z; As[kq + 3][row] = va.w;
            float4 vb = *(const float4*)(Bb + (size_t)row * E_DIM + k0 + kq);
            Bs[kq + 0][row] = vb.x; Bs[kq + 1][row] = vb.y;
            Bs[kq + 2][row] = vb.z; Bs[kq + 3][row] = vb.w;
        }
        __syncthreads();
#pragma unroll
        for (int kk = 0; kk < 16; kk++) {
            float ra[8], rb[8];
            *(float4*)&ra[0] = *(const float4*)&As[kk][ty * 8];
            *(float4*)&ra[4] = *(const float4*)&As[kk][ty * 8 + 4];
            *(float4*)&rb[0] = *(const float4*)&Bs[kk][tx * 8];
            *(float4*)&rb[4] = *(const float4*)&Bs[kk][tx * 8 + 4];
#pragma unroll
            for (int i = 0; i < 8; i++)
#pragma unroll
                for (int j = 0; j < 8; j++)
                    acc[i][j] += ra[i] * rb[j];
        }
        __syncthreads();
    }
    int colBase = blockIdx.y * 128 + tx * 8;
#pragma unroll
    for (int i = 0; i < 8; i++) {
        size_t row = (size_t)blockIdx.x * 128 + ty * 8 + i;
        float4 v0, v1;
        v0.x = acc[i][0] + b2[colBase + 0]; v0.y = acc[i][1] + b2[colBase + 1];
        v0.z = acc[i][2] + b2[colBase + 2]; v0.w = acc[i][3] + b2[colBase + 3];
        v1.x = acc[i][4] + b2[colBase + 4]; v1.y = acc[i][5] + b2[colBase + 5];
        v1.z = acc[i][6] + b2[colBase + 6]; v1.w = acc[i][7] + b2[colBase + 7];
        *(float4*)(g_ocb + row * D_IN + colBase)     = v0;
        *(float4*)(g_ocb + row * D_IN + colBase + 4) = v1;
    }
}

__global__ void k_final(const float* __restrict__ x, float* __restrict__ out) {
    int t = threadIdx.x;
    float* outq = out + 1;
    double accd = 0.0;
#pragma unroll
    for (int r = 0; r < 8; r++) {
        int n = blockIdx.x * 8 + r;
        int idx = (int)(g_amin[n] & 0xFFFFFFFFull);
        float4 q  = ((const float4*)(g_ocb + (size_t)idx * D_IN))[t];
        float4 xv = ((const float4*)(x + (size_t)n * D_IN))[t];
        float dx = __fsub_rn(q.x, xv.x);
        float dy = __fsub_rn(q.y, xv.y);
        float dz = __fsub_rn(q.z, xv.z);
        float dw = __fsub_rn(q.w, xv.w);
        float* o = outq + (size_t)n * D_IN + t * 4;
        o[0] = __fadd_rn(xv.x, dx);
        o[1] = __fadd_rn(xv.y, dy);
        o[2] = __fadd_rn(xv.z, dz);
        o[3] = __fadd_rn(xv.w, dw);
        accd += (double)dx * dx + (double)dy * dy + (double)dz * dz + (double)dw * dw;
    }
    __shared__ double sd[256];
    sd[t] = accd; __syncthreads();
    for (int s = 128; s > 0; s >>= 1) { if (t < s) sd[t] += sd[t + s]; __syncthreads(); }
    if (t == 0) atomicAdd(&g_loss, sd[0]);
}

__global__ void k_small(float* __restrict__ out) {
    int i = blockIdx.x * 256 + threadIdx.x;
    size_t OFF_U = 1 + (size_t)N_TOK * D_IN;
    if (i == 0) out[0] = (float)(1.25 * g_loss / ((double)N_TOK * (double)D_IN));
    if (i < K_CB) out[OFF_U + i] = (float)g_hist[i] / (float)N_TOK;
}

__global__ void k_embcopy(const float* __restrict__ emb, float* __restrict__ out) {
    size_t OFF_E = 1 + (size_t)N_TOK * D_IN + K_CB;
    int i = blockIdx.x * 256 + threadIdx.x;
    out[OFF_E + i] = emb[i];
}

// ================= launch =================
#define MM_SMEM (8 * 128 * STR * 4 + 512 * 4)   // 81920 + 2048

extern "C" void kernel_launch(void* const* d_in, const int* in_sizes, int n_in,
                              void* d_out, int out_size) {
    (void)in_sizes; (void)n_in; (void)out_size;
    const float* x      = (const float*)d_in[0];
    const float* emb    = (const float*)d_in[1];
    const float* w1     = (const float*)d_in[2];
    const float* b1     = (const float*)d_in[3];
    const float* w2     = (const float*)d_in[4];
    const float* b2     = (const float*)d_in[5];
    const float* gamma1 = (const float*)d_in[6];
    const float* beta1  = (const float*)d_in[7];
    const float* gamma2 = (const float*)d_in[8];
    const float* beta2  = (const float*)d_in[9];
    float* out = (float*)d_out;

    cudaFuncSetAttribute(k_mm1,  cudaFuncAttributeMaxDynamicSharedMemorySize, MM_SMEM);
    cudaFuncSetAttribute(k_dist, cudaFuncAttributeMaxDynamicSharedMemorySize, MM_SMEM);

    k_init<<<256, 256>>>();
    k_colstats<<<dim3(D_IN / 256, SLABS), 256>>>(x);
    k_bn1fin<<<D_IN / 256, 256>>>(gamma1, beta1);
    k_fold<<<E_DIM, 256>>>(w1, b1);
    k_mm1<<<dim3(N_TOK / 128, 2), 256, MM_SMEM>>>(x);
    k_ee<<<K_CB / 8, 256>>>(emb);
    k_dist<<<dim3(N_TOK / 128, K_CB / 128), 256, MM_SMEM>>>(emb);
    k_histo<<<N_TOK / 256, 256>>>();
    k_bn2<<<E_DIM, 256>>>(emb, gamma2, beta2);
    k_qn<<<(K_CB * E_DIM) / 256, 256>>>(emb);
    k_gemm2<<<dim3(K_CB / 128, D_IN / 128), 256>>>(w2, b2);
    k_final<<<N_TOK / 8, 256>>>(x, out);
    k_small<<<4, 256>>>(out);
    k_embcopy<<<(K_CB * E_DIM) / 256, 256>>>(emb, out);
}